// round 6
// baseline (speedup 1.0000x reference)
#include <cuda_runtime.h>
#include <cuda_bf16.h>
#include <cstdint>

// MultiPrototypeLoss — persistent kernel with cp.async.bulk row pipeline.
// B=16384 rows, C=1000 classes, P=4; 262MB once-read stream (HBM-bound).
// d[b,c] = -logsumexp(-x[b,4c..4c+3]); loss = mean_b (d[b,l]/out_mean)^2.
//
// R3 (LDG, block-per-row) peaked at 74% DRAM: in-flight bytes were capped by
// the 32-reg budget at full occupancy (4x LDG.128/thread). Here the bulk-copy
// engine keeps a whole 16000B row in flight per block slot with zero register
// cost: 2-slot smem ring + mbarrier, compute reads via LDS.
// Labels: runtime int32/int64 detection (JAX x64 ambiguity).

#define NUM_C     1000
#define ROW_BYTES (NUM_C * 16)     // 16000
#define THREADS   512
#define GRID      (148 * 4)        // 4 blocks/SM, 64 warps/SM
#define NSLOTS    2

__device__ double   g_acc   = 0.0;
__device__ unsigned g_count = 0u;

__device__ __forceinline__ uint32_t smem_u32(const void* p) {
    return (uint32_t)__cvta_generic_to_shared(p);
}
__device__ __forceinline__ void mbar_init(uint32_t mbar, uint32_t cnt) {
    asm volatile("mbarrier.init.shared.b64 [%0], %1;" :: "r"(mbar), "r"(cnt) : "memory");
}
__device__ __forceinline__ void mbar_expect_tx(uint32_t mbar, uint32_t bytes) {
    asm volatile("mbarrier.arrive.expect_tx.shared.b64 _, [%0], %1;"
                 :: "r"(mbar), "r"(bytes) : "memory");
}
__device__ __forceinline__ void mbar_arrive(uint32_t mbar) {
    asm volatile("mbarrier.arrive.shared.b64 _, [%0];" :: "r"(mbar) : "memory");
}
__device__ __forceinline__ void mbar_wait(uint32_t mbar, uint32_t parity) {
    asm volatile(
        "{\n\t.reg .pred P;\n\t"
        "WL%=:\n\t"
        "mbarrier.try_wait.parity.acquire.cta.shared::cta.b64 P, [%0], %1, 0x989680;\n\t"
        "@P bra WD%=;\n\t"
        "bra WL%=;\n\t"
        "WD%=:\n\t}"
        :: "r"(mbar), "r"(parity) : "memory");
}
__device__ __forceinline__ void bulk_copy(uint32_t dst_smem, const void* src, uint32_t bytes, uint32_t mbar) {
    asm volatile(
        "cp.async.bulk.shared::cta.global.mbarrier::complete_tx::bytes [%0], [%1], %2, [%3];"
        :: "r"(dst_smem), "l"(src), "r"(bytes), "r"(mbar) : "memory");
}

__device__ __forceinline__ float softmin4(float4 v) {
    float m = fminf(fminf(v.x, v.y), fminf(v.z, v.w));
    float s = __expf(m - v.x) + __expf(m - v.y) +
              __expf(m - v.z) + __expf(m - v.w);
    return m - __logf(s);   // = -logsumexp(-v)
}

__global__ __launch_bounds__(THREADS, 4) void mpl_kernel(
    const char* __restrict__ dist_bytes,   // [B, NUM_C] float4 groups (bytes)
    const int*  __restrict__ labels_raw,   // [B] int32 OR int64 (as words)
    float*      __restrict__ out,
    int B)
{
    __shared__ alignas(16) char buf[NSLOTS][ROW_BYTES];
    __shared__ unsigned long long mbar_full_s[NSLOTS];
    __shared__ unsigned long long mbar_empty_s[NSLOTS];
    __shared__ float s_sum[2][THREADS / 32];
    __shared__ float s_in [2][THREADS / 32];

    const int tid = threadIdx.x;
    const int lid = tid & 31;
    const int wid = tid >> 5;

    const uint32_t full0  = smem_u32(&mbar_full_s[0]);
    const uint32_t full1  = smem_u32(&mbar_full_s[1]);
    const uint32_t empty0 = smem_u32(&mbar_empty_s[0]);
    const uint32_t empty1 = smem_u32(&mbar_empty_s[1]);
    const uint32_t buf0   = smem_u32(&buf[0][0]);
    const uint32_t buf1   = smem_u32(&buf[1][0]);

    if (tid == 0) {
        mbar_init(full0, 1);  mbar_init(full1, 1);
        mbar_init(empty0, 1); mbar_init(empty1, 1);
    }

    // --- inline label-dtype detection (2KB broadcast read per block) ---
    int odd_idx = 2 * tid + 1;
    int nz = (odd_idx < B) ? (labels_raw[odd_idx] != 0) : 0;
    const int labels_are_i32 = __syncthreads_or(nz);   // also orders mbar init

    // local rows: row = blockIdx.x + i*GRID, i in [0, n)
    const int n = (blockIdx.x < B) ? ((B - 1 - blockIdx.x) / GRID + 1) : 0;

    double local_acc = 0.0;   // meaningful on tid 0

    // prologue: issue row 0
    if (tid == 0 && n > 0) {
        mbar_expect_tx(full0, ROW_BYTES);
        bulk_copy(buf0, dist_bytes + (size_t)blockIdx.x * ROW_BYTES, ROW_BYTES, full0);
    }

    for (int i = 0; i < n; i++) {
        const int slot = i & 1;
        const int row  = blockIdx.x + i * GRID;

        // producer: issue row i+1 into the other slot
        if (tid == 0 && i + 1 < n) {
            const int j = i + 1;
            const uint32_t fsl = (j & 1) ? full1 : full0;
            const uint32_t esl = (j & 1) ? empty1 : empty0;
            if (j >= NSLOTS)                    // wait prior consume of slot
                mbar_wait(esl, ((j >> 1) - 1) & 1);
            mbar_expect_tx(fsl, ROW_BYTES);
            bulk_copy((j & 1) ? buf1 : buf0,
                      dist_bytes + (size_t)(row + GRID) * ROW_BYTES,
                      ROW_BYTES, fsl);
        }

        const int lbl = labels_are_i32 ? labels_raw[row] : labels_raw[2 * row];

        // consumer: wait for row i
        mbar_wait(slot ? full1 : full0, (i >> 1) & 1);

        const float4* bp = (const float4*)(slot ? &buf[1][0] : &buf[0][0]);
        float4 v0 = bp[tid];
        const bool h = (tid < NUM_C - THREADS);   // tid < 488
        float4 v1;
        if (h) v1 = bp[tid + THREADS];

        float d0 = softmin4(v0);
        float d1 = h ? softmin4(v1) : 0.0f;

        float sum_d = d0 + d1;
        float in_cls = 0.0f;
        if (tid == lbl) in_cls = d0;
        if (h && tid + THREADS == lbl) in_cls = d1;

#pragma unroll
        for (int off = 16; off > 0; off >>= 1) {
            sum_d  += __shfl_xor_sync(0xFFFFFFFFu, sum_d,  off);
            in_cls += __shfl_xor_sync(0xFFFFFFFFu, in_cls, off);
        }
        if (lid == 0) { s_sum[slot][wid] = sum_d; s_in[slot][wid] = in_cls; }
        __syncthreads();    // slot fully consumed + partials visible

        if (tid == 0) {
            mbar_arrive(slot ? empty1 : empty0);   // free slot for producer
            float tot = 0.0f, inc = 0.0f;
#pragma unroll
            for (int w = 0; w < THREADS / 32; w++) { tot += s_sum[slot][w]; inc += s_in[slot][w]; }
            float out_mean = (tot - inc) * (1.0f / (NUM_C - 1));
            float r = inc / out_mean;
            local_acc += (double)(r * r);
        }
    }

    if (tid == 0) {
        atomicAdd(&g_acc, local_acc);
        __threadfence();
        unsigned t = atomicAdd(&g_count, 1u);
        if (t == gridDim.x - 1) {          // last block: finalize + reset
            double a = atomicAdd(&g_acc, 0.0);
            *out = (float)(a / (double)B);
            g_acc   = 0.0;                 // restore invariant for replay
            g_count = 0u;
        }
    }
}

extern "C" void kernel_launch(void* const* d_in, const int* in_sizes, int n_in,
                              void* d_out, int out_size) {
    const char* dist   = (const char*)d_in[0];
    const int*  labels = (const int*)d_in[1];
    float*      out    = (float*)d_out;
    const int B = in_sizes[1];   // label element count == batch size

    mpl_kernel<<<GRID, THREADS>>>(dist, labels, out, B);
}

// round 7
// speedup vs baseline: 1.2367x; 1.2367x over previous
#include <cuda_runtime.h>
#include <cuda_bf16.h>

// MultiPrototypeLoss — persistent block-per-row kernel (R3 + slim epilogue).
// B=16384 rows, C=1000 classes, P=4; 262MB once-read stream (HBM-bound).
// d[b,c] = -logsumexp(-x[b,4c..4c+3]); loss = mean_b (d[b,l]/out_mean)^2.
//
// vs R3 (74% DRAM): in_cls is written directly by the owning thread
// (cls = tid mod 256 -> exactly one owner per row), removing 5 of 10
// shuffles; and partials are parity double-buffered, removing the second
// __syncthreads per row. Loads unchanged: 4 front-batched LDG.128/thread.
// Labels: runtime int32/int64 detection (JAX x64 ambiguity).

#define NUM_C   1000
#define THREADS 256
#define WARPS   (THREADS / 32)
#define GRID    (148 * 8)       // full residency: 8 blocks/SM @ 256 thr

__device__ double   g_acc   = 0.0;
__device__ unsigned g_count = 0u;

__device__ __forceinline__ float softmin4(float4 v) {
    float m = fminf(fminf(v.x, v.y), fminf(v.z, v.w));
    float s = __expf(m - v.x) + __expf(m - v.y) +
              __expf(m - v.z) + __expf(m - v.w);
    return m - __logf(s);   // = -logsumexp(-v)
}

__global__ __launch_bounds__(THREADS) void mpl_kernel(
    const float4* __restrict__ dist,       // [B, NUM_C] float4 groups
    const int*    __restrict__ labels_raw, // [B] int32 OR int64 (as words)
    float*        __restrict__ out,
    int B)
{
    const int tid = threadIdx.x;
    const int lid = tid & 31;
    const int wid = tid >> 5;

    // --- inline label-dtype detection (1KB broadcast read per block) ---
    int odd_idx = 2 * tid + 1;
    int nz = (odd_idx < B) ? (labels_raw[odd_idx] != 0) : 0;
    const int labels_are_i32 = __syncthreads_or(nz);

    __shared__ float s_sum[2][WARPS];
    __shared__ float s_in[2];

    const int c0 = tid;
    const int c1 = tid + THREADS;
    const int c2 = tid + 2 * THREADS;
    const int c3 = tid + 3 * THREADS;
    const bool has3 = (c3 < NUM_C);          // tid < 232

    double local_acc = 0.0;                  // meaningful on tid 0
    int par = 0;

    for (int row = blockIdx.x; row < B; row += gridDim.x, par ^= 1) {
        const float4* rowp = dist + (size_t)row * NUM_C;
        const int lbl = labels_are_i32 ? labels_raw[row]
                                       : labels_raw[2 * row];

        // 4 front-batched independent LDG.128 (512B coalesced warp-fronts)
        float4 v0 = __ldcs(rowp + c0);
        float4 v1 = __ldcs(rowp + c1);
        float4 v2 = __ldcs(rowp + c2);
        float4 v3;
        if (has3) v3 = __ldcs(rowp + c3);

        float d0 = softmin4(v0);
        float d1 = softmin4(v1);
        float d2 = softmin4(v2);
        float d3 = has3 ? softmin4(v3) : 0.0f;

        float sum_d = (d0 + d1) + (d2 + d3);

        // exactly one thread in the block owns class `lbl` -> direct STS
        if (c0 == lbl) s_in[par] = d0;
        if (c1 == lbl) s_in[par] = d1;
        if (c2 == lbl) s_in[par] = d2;
        if (c3 == lbl) s_in[par] = d3;       // implies has3 since lbl<1000

        // warp reduce sum only (5 shuffles)
#pragma unroll
        for (int off = 16; off > 0; off >>= 1)
            sum_d += __shfl_xor_sync(0xFFFFFFFFu, sum_d, off);
        if (lid == 0) s_sum[par][wid] = sum_d;

        __syncthreads();   // single barrier per row (parity protects reuse)

        if (tid == 0) {
            float tot = 0.0f;
#pragma unroll
            for (int w = 0; w < WARPS; w++) tot += s_sum[par][w];
            float inc = s_in[par];
            float out_mean = (tot - inc) * (1.0f / (NUM_C - 1));
            float r = inc / out_mean;
            local_acc += (double)(r * r);
        }
    }

    if (tid == 0) {
        atomicAdd(&g_acc, local_acc);
        __threadfence();
        unsigned t = atomicAdd(&g_count, 1u);
        if (t == gridDim.x - 1) {          // last block: finalize + reset
            double a = atomicAdd(&g_acc, 0.0);
            *out = (float)(a / (double)B);
            g_acc   = 0.0;                 // restore invariant for replay
            g_count = 0u;
        }
    }
}

extern "C" void kernel_launch(void* const* d_in, const int* in_sizes, int n_in,
                              void* d_out, int out_size) {
    const float4* dist   = (const float4*)d_in[0];
    const int*    labels = (const int*)d_in[1];
    float*        out    = (float*)d_out;
    const int B = in_sizes[1];   // label element count == batch size

    mpl_kernel<<<GRID, THREADS>>>(dist, labels, out, B);
}

// round 8
// speedup vs baseline: 1.2534x; 1.0134x over previous
#include <cuda_runtime.h>
#include <cuda_bf16.h>

// MultiPrototypeLoss — persistent block-per-row kernel, software-pipelined.
// B=16384 rows, C=1000 classes, P=4; 262MB once-read stream (HBM-bound).
// d[b,c] = -logsumexp(-x[b,4c..4c+3]); loss = mean_b (d[b,l]/out_mean)^2.
//
// R3/R7 both hit exactly 45.18us @ 74% DRAM. Remaining candidate bubble:
// next-row LDGs only issue after the per-row __syncthreads (ptxas won't
// hoist LDG across BAR). Here next-row loads are issued into the just-freed
// v registers BEFORE the reduce/barrier/epilogue, keeping the L1tex queue
// fed through the sync. Liveness stays ~4 float4 -> 32-reg / 8-block pin.
// Labels: runtime int32/int64 detection (JAX x64 ambiguity).

#define NUM_C   1000
#define THREADS 256
#define WARPS   (THREADS / 32)
#define GRID    (148 * 8)       // full residency: 8 blocks/SM @ 256 thr

__device__ double   g_acc   = 0.0;
__device__ unsigned g_count = 0u;

__device__ __forceinline__ float softmin4(float4 v) {
    float m = fminf(fminf(v.x, v.y), fminf(v.z, v.w));
    float s = __expf(m - v.x) + __expf(m - v.y) +
              __expf(m - v.z) + __expf(m - v.w);
    return m - __logf(s);   // = -logsumexp(-v)
}

__global__ __launch_bounds__(THREADS, 8) void mpl_kernel(
    const float4* __restrict__ dist,       // [B, NUM_C] float4 groups
    const int*    __restrict__ labels_raw, // [B] int32 OR int64 (as words)
    float*        __restrict__ out,
    int B)
{
    const int tid = threadIdx.x;
    const int lid = tid & 31;
    const int wid = tid >> 5;

    // --- inline label-dtype detection (1KB broadcast read per block) ---
    int odd_idx = 2 * tid + 1;
    int nz = (odd_idx < B) ? (labels_raw[odd_idx] != 0) : 0;
    const int labels_are_i32 = __syncthreads_or(nz);

    __shared__ float s_sum[2][WARPS];
    __shared__ float s_in[2];

    const int c0 = tid;
    const int c1 = tid + THREADS;
    const int c2 = tid + 2 * THREADS;
    const int c3 = tid + 3 * THREADS;
    const bool has3 = (c3 < NUM_C);          // tid < 232

    double local_acc = 0.0;                  // meaningful on tid 0
    int par = 0;

    // ---- prologue: load first row ----
    int row = blockIdx.x;
    float4 v0, v1, v2, v3;
    int lbl = 0;
    if (row < B) {
        const float4* rowp = dist + (size_t)row * NUM_C;
        lbl = labels_are_i32 ? labels_raw[row] : labels_raw[2 * row];
        v0 = __ldcs(rowp + c0);
        v1 = __ldcs(rowp + c1);
        v2 = __ldcs(rowp + c2);
        if (has3) v3 = __ldcs(rowp + c3);
    }

    while (row < B) {
        // consume v -> d (v registers become dead here)
        float d0 = softmin4(v0);
        float d1 = softmin4(v1);
        float d2 = softmin4(v2);
        float d3 = has3 ? softmin4(v3) : 0.0f;

        // ---- prefetch next row into the freed v registers (pre-barrier) ----
        const int nrow = row + GRID;
        const int cur_lbl = lbl;
        if (nrow < B) {
            const float4* nrowp = dist + (size_t)nrow * NUM_C;
            lbl = labels_are_i32 ? labels_raw[nrow] : labels_raw[2 * nrow];
            v0 = __ldcs(nrowp + c0);
            v1 = __ldcs(nrowp + c1);
            v2 = __ldcs(nrowp + c2);
            if (has3) v3 = __ldcs(nrowp + c3);
        }

        // ---- epilogue for current row (loads in flight above) ----
        float sum_d = (d0 + d1) + (d2 + d3);

        // exactly one thread in the block owns class cur_lbl -> direct STS
        if (c0 == cur_lbl) s_in[par] = d0;
        if (c1 == cur_lbl) s_in[par] = d1;
        if (c2 == cur_lbl) s_in[par] = d2;
        if (c3 == cur_lbl) s_in[par] = d3;

#pragma unroll
        for (int off = 16; off > 0; off >>= 1)
            sum_d += __shfl_xor_sync(0xFFFFFFFFu, sum_d, off);
        if (lid == 0) s_sum[par][wid] = sum_d;

        __syncthreads();   // single barrier per row (parity protects reuse)

        if (tid == 0) {
            float tot = 0.0f;
#pragma unroll
            for (int w = 0; w < WARPS; w++) tot += s_sum[par][w];
            float inc = s_in[par];
            float out_mean = (tot - inc) * (1.0f / (NUM_C - 1));
            float r = inc / out_mean;
            local_acc += (double)(r * r);
        }

        row = nrow;
        par ^= 1;
    }

    if (tid == 0) {
        atomicAdd(&g_acc, local_acc);
        __threadfence();
        unsigned t = atomicAdd(&g_count, 1u);
        if (t == gridDim.x - 1) {          // last block: finalize + reset
            double a = atomicAdd(&g_acc, 0.0);
            *out = (float)(a / (double)B);
            g_acc   = 0.0;                 // restore invariant for replay
            g_count = 0u;
        }
    }
}

extern "C" void kernel_launch(void* const* d_in, const int* in_sizes, int n_in,
                              void* d_out, int out_size) {
    const float4* dist   = (const float4*)d_in[0];
    const int*    labels = (const int*)d_in[1];
    float*        out    = (float*)d_out;
    const int B = in_sizes[1];   // label element count == batch size

    mpl_kernel<<<GRID, THREADS>>>(dist, labels, out, B);
}

// round 9
// speedup vs baseline: 1.3022x; 1.0390x over previous
#include <cuda_runtime.h>
#include <cuda_bf16.h>

// MultiPrototypeLoss — persistent block-per-row, DYNAMIC row scheduling.
// B=16384, C=1000, P=4; 262MB once-read stream.
// d[b,c] = -logsumexp(-x[b,4c..4c+3]); loss = mean_b (d[b,l]/out_mean)^2.
//
// R3/R7/R8 all converge at 75% DRAM-active with occ 94% -> DRAM idles 25%.
// Cause (B300 spread model): static 13-14 rows/block + ~1.3x cross-CTA
// L1tex spread -> fast blocks idle at the tail. Fix: atomic row counter,
// grabbed two rows ahead (latency hidden behind the row period).
// Also: per-thread log-folding  sum d = sum m - log(prod s)  (MUFU 20->17).
// Labels: runtime int32/int64 detection (JAX x64 ambiguity).

#define NUM_C   1000
#define THREADS 256
#define WARPS   (THREADS / 32)
#define GRID    (148 * 8)       // full residency: 8 blocks/SM @ 256 thr

__device__ double   g_acc   = 0.0;
__device__ unsigned g_count = 0u;
__device__ unsigned g_row   = GRID;   // next unclaimed row (reset each run)

__global__ __launch_bounds__(THREADS, 8) void mpl_kernel(
    const float4* __restrict__ dist,       // [B, NUM_C] float4 groups
    const int*    __restrict__ labels_raw, // [B] int32 OR int64 (as words)
    float*        __restrict__ out,
    int B)
{
    const int tid = threadIdx.x;
    const int lid = tid & 31;
    const int wid = tid >> 5;

    __shared__ int   s_next[2];
    __shared__ float s_sum[2][WARPS];
    __shared__ float s_in_m[2];
    __shared__ float s_in_s[2];

    // prologue grab of r1 (r0 = blockIdx.x is static)
    if (tid == 0) s_next[0] = (int)atomicAdd(&g_row, 1u);

    // --- inline label-dtype detection (1KB broadcast read per block) ---
    int odd_idx = 2 * tid + 1;
    int nz = (odd_idx < B) ? (labels_raw[odd_idx] != 0) : 0;
    const int labels_are_i32 = __syncthreads_or(nz);   // also orders s_next

    const int c0 = tid;
    const int c1 = tid + THREADS;
    const int c2 = tid + 2 * THREADS;
    const int c3 = tid + 3 * THREADS;
    const bool has3 = (c3 < NUM_C);          // tid < 232

    double local_acc = 0.0;                  // meaningful on tid 0
    int par = 0;

    int row  = blockIdx.x;                   // r_i
    int rown = s_next[0];                    // r_{i+1}

    // ---- prologue: load first row ----
    float4 v0, v1, v2, v3;
    int lbl = 0;
    if (row < B) {
        const float4* rowp = dist + (size_t)row * NUM_C;
        lbl = labels_are_i32 ? labels_raw[row] : labels_raw[2 * row];
        v0 = __ldcs(rowp + c0);
        v1 = __ldcs(rowp + c1);
        v2 = __ldcs(rowp + c2);
        if (has3) v3 = __ldcs(rowp + c3);
    }

    while (row < B) {
        const int cur_lbl = lbl;

        // ---- per-group softmin pieces; fold logs:  d_sum = Σm - log(Πs) ----
        float mm, sp;
        {
            float m = fminf(fminf(v0.x, v0.y), fminf(v0.z, v0.w));
            float s = (__expf(m - v0.x) + __expf(m - v0.y)) +
                      (__expf(m - v0.z) + __expf(m - v0.w));
            if (c0 == cur_lbl) { s_in_m[par] = m; s_in_s[par] = s; }
            mm = m; sp = s;
        }
        {
            float m = fminf(fminf(v1.x, v1.y), fminf(v1.z, v1.w));
            float s = (__expf(m - v1.x) + __expf(m - v1.y)) +
                      (__expf(m - v1.z) + __expf(m - v1.w));
            if (c1 == cur_lbl) { s_in_m[par] = m; s_in_s[par] = s; }
            mm += m; sp *= s;
        }
        {
            float m = fminf(fminf(v2.x, v2.y), fminf(v2.z, v2.w));
            float s = (__expf(m - v2.x) + __expf(m - v2.y)) +
                      (__expf(m - v2.z) + __expf(m - v2.w));
            if (c2 == cur_lbl) { s_in_m[par] = m; s_in_s[par] = s; }
            mm += m; sp *= s;
        }
        if (has3) {
            float m = fminf(fminf(v3.x, v3.y), fminf(v3.z, v3.w));
            float s = (__expf(m - v3.x) + __expf(m - v3.y)) +
                      (__expf(m - v3.z) + __expf(m - v3.w));
            if (c3 == cur_lbl) { s_in_m[par] = m; s_in_s[par] = s; }
            mm += m; sp *= s;
        }

        // ---- prefetch r_{i+1} into freed v registers (pre-barrier) ----
        if (rown < B) {
            const float4* nrowp = dist + (size_t)rown * NUM_C;
            lbl = labels_are_i32 ? labels_raw[rown] : labels_raw[2 * rown];
            v0 = __ldcs(nrowp + c0);
            v1 = __ldcs(nrowp + c1);
            v2 = __ldcs(nrowp + c2);
            if (has3) v3 = __ldcs(nrowp + c3);
        }

        // ---- grab r_{i+2} (latency hidden; consumed after next barrier) ----
        if (tid == 0) s_next[par ^ 1] = (int)atomicAdd(&g_row, 1u);

        // ---- epilogue for current row ----
        float sum_d = mm - __logf(sp);
#pragma unroll
        for (int off = 16; off > 0; off >>= 1)
            sum_d += __shfl_xor_sync(0xFFFFFFFFu, sum_d, off);
        if (lid == 0) s_sum[par][wid] = sum_d;

        __syncthreads();   // single barrier per row (parity protects reuse)

        if (tid == 0) {
            float tot = 0.0f;
#pragma unroll
            for (int w = 0; w < WARPS; w++) tot += s_sum[par][w];
            float inc = s_in_m[par] - __logf(s_in_s[par]);
            float out_mean = (tot - inc) * (1.0f / (NUM_C - 1));
            float r = inc / out_mean;
            local_acc += (double)(r * r);
        }

        row  = rown;
        rown = s_next[par ^ 1];   // r_{i+2}, visible post-barrier
        par ^= 1;
    }

    if (tid == 0) {
        atomicAdd(&g_acc, local_acc);
        __threadfence();
        unsigned t = atomicAdd(&g_count, 1u);
        if (t == gridDim.x - 1) {          // last block: finalize + reset
            double a = atomicAdd(&g_acc, 0.0);
            *out = (float)(a / (double)B);
            g_acc   = 0.0;                 // restore invariants for replay
            g_count = 0u;
            g_row   = GRID;
        }
    }
}

extern "C" void kernel_launch(void* const* d_in, const int* in_sizes, int n_in,
                              void* d_out, int out_size) {
    const float4* dist   = (const float4*)d_in[0];
    const int*    labels = (const int*)d_in[1];
    float*        out    = (float*)d_out;
    const int B = in_sizes[1];   // label element count == batch size

    mpl_kernel<<<GRID, THREADS>>>(dist, labels, out, B);
}